// round 16
// baseline (speedup 1.0000x reference)
#include <cuda_runtime.h>
#include <cuda_fp16.h>
#include <cstddef>

#define BB 4
#define CC 256
#define LSEQ 2048
#define NH 8
#define DH 32
#define EPSV 1e-5f
#define CHUNKS (LSEQ / 128)              // 16 chunks of 128 keys

// ---- helpers --------------------------------------------------------------
// m16n8k16 f16 MMA, fp32 accum
__device__ __forceinline__ void mma_f16(float* d, const unsigned* a,
                                        unsigned b0, unsigned b1) {
    asm("mma.sync.aligned.m16n8k16.row.col.f32.f16.f16.f32 "
        "{%0,%1,%2,%3},{%4,%5,%6,%7},{%8,%9},{%0,%1,%2,%3};"
        : "+f"(d[0]), "+f"(d[1]), "+f"(d[2]), "+f"(d[3])
        : "r"(a[0]), "r"(a[1]), "r"(a[2]), "r"(a[3]), "r"(b0), "r"(b1));
}
__device__ __forceinline__ unsigned packh2(float a, float b) {
    __half2 h = __floats2half2_rn(a, b);
    return *(unsigned*)&h;
}
__device__ __forceinline__ unsigned ex2h2(unsigned x) {
    unsigned y;
    asm("ex2.approx.f16x2 %0,%1;" : "=r"(y) : "r"(x));
    return y;
}
__device__ __forceinline__ void cpa16(unsigned dst, const void* src) {
    asm volatile("cp.async.cg.shared.global [%0], [%1], 16;" :: "r"(dst), "l"(src));
}
__device__ __forceinline__ void cpcommit() {
    asm volatile("cp.async.commit_group;");
}
template <int N>
__device__ __forceinline__ void cpwait() {
    asm volatile("cp.async.wait_group %0;" :: "n"(N));
}

// Scratch
__device__ __half g_wh[4 * CC * CC];              // wq,wk,wv,wo in half [o][k]
__device__ __half g_xpet[3 * BB * LSEQ * CC];     // (X+PE)^T half [pid][b][l][c]
__device__ __half g_qh[BB * CC * LSEQ];           // [b][h*32+d][l]
__device__ __half g_kh[BB * NH * LSEQ * DH];      // [b][h][m][d]
__device__ __half g_vh[BB * CC * LSEQ];           // [b][h*32+d][m]
__device__ __half g_aht[BB * LSEQ * CC];          // att TRANSPOSED [b][l][c]

// ---------------------------------------------------------------------------
// Prepass 1: convert wq/wk/wv/wo to half.
// ---------------------------------------------------------------------------
__global__ __launch_bounds__(256) void conv_w(
    const float* __restrict__ wq, const float* __restrict__ wk,
    const float* __restrict__ wv, const float* __restrict__ wo,
    __half* __restrict__ wh)
{
    const int pid = blockIdx.y;
    const float* W = pid == 0 ? wq : (pid == 1 ? wk : (pid == 2 ? wv : wo));
    int i = (blockIdx.x * 256 + threadIdx.x) * 4;
    float4 f = *(const float4*)&W[i];
    __half2 h0 = __floats2half2_rn(f.x, f.y);
    __half2 h1 = __floats2half2_rn(f.z, f.w);
    __half2* dst = (__half2*)&wh[pid * CC * CC + i];
    dst[0] = h0;
    dst[1] = h1;
}

// ---------------------------------------------------------------------------
// Prepass 2: XPE^T[pid][b][l][c] = half(X[b][c][l] + PE[c][l]).  32x32 tiles.
// ---------------------------------------------------------------------------
__global__ __launch_bounds__(256) void prep_xpe(
    const float* __restrict__ qx, const float* __restrict__ kx,
    const float* __restrict__ vx,
    const float* __restrict__ pe_q, const float* __restrict__ pe_vk,
    __half* __restrict__ xpet)
{
    __shared__ float T[32][33];
    const int pid = blockIdx.z / BB;
    const int b   = blockIdx.z % BB;
    const int c0 = blockIdx.y * 32, l0 = blockIdx.x * 32;
    const int tid = threadIdx.x;
    const float* X  = pid == 0 ? qx : (pid == 1 ? kx : vx);
    const float* PE = pid == 0 ? pe_q : pe_vk;

    #pragma unroll
    for (int i = tid; i < 1024; i += 256) {
        int c = i >> 5, l = i & 31;
        size_t off = (size_t)(c0 + c) * LSEQ + l0 + l;
        T[c][l] = X[(size_t)b * CC * LSEQ + off] + PE[off];
    }
    __syncthreads();
    #pragma unroll
    for (int i = tid; i < 1024; i += 256) {
        int l = i >> 5, c = i & 31;
        xpet[((size_t)(pid * BB + b) * LSEQ + l0 + l) * CC + c0 + c] =
            __float2half_rn(T[c][l]);
    }
}

// ---------------------------------------------------------------------------
// Fused Q/K/V projection: all-f16 MMA, cp.async double-buffered.
// ---------------------------------------------------------------------------
__global__ __launch_bounds__(256, 2) void proj_all(
    const __half* __restrict__ wh, const __half* __restrict__ xpet,
    const float* __restrict__ bq, const float* __restrict__ gq,
    const float* __restrict__ betaq, const float* __restrict__ mq,
    const float* __restrict__ varq,
    const float* __restrict__ bk, const float* __restrict__ gk,
    const float* __restrict__ betak, const float* __restrict__ mk,
    const float* __restrict__ vark,
    const float* __restrict__ bv, const float* __restrict__ gv,
    const float* __restrict__ betav, const float* __restrict__ mv,
    const float* __restrict__ varv,
    float qsc,
    __half* __restrict__ qh, __half* __restrict__ kh, __half* __restrict__ vh)
{
    __shared__ __align__(16) __half Ah[2][64][40];    // [o][kk]
    __shared__ __align__(16) __half Bh[2][128][40];   // [l][kk]

    const int pid = blockIdx.z / BB;
    const int b   = blockIdx.z % BB;
    const int o0 = blockIdx.y * 64;
    const int l0 = blockIdx.x * 128;
    const int tid = threadIdx.x;
    const int w = tid >> 5, lane = tid & 31;
    const int g = lane >> 2, t = lane & 3;
    const int om = (w >> 2) * 32;
    const int on = (w & 3) * 32;

    const float *bias, *gg, *beta, *mean, *var;
    __half* OUT;
    float outscale;
    if (pid == 0) {
        bias = bq; gg = gq; beta = betaq; mean = mq; var = varq;
        outscale = qsc; OUT = qh;
    } else if (pid == 1) {
        bias = bk; gg = gk; beta = betak; mean = mk; var = vark;
        outscale = 1.f; OUT = kh;
    } else {
        bias = bv; gg = gv; beta = betav; mean = mv; var = varv;
        outscale = 1.f; OUT = vh;
    }
    const __half* Wp = wh + pid * CC * CC;
    const __half* Xp = xpet + (size_t)(pid * BB + b) * LSEQ * CC;

    auto load_stage = [&](int s, int k0) {
        {
            int o = tid >> 2, seg = (tid & 3) * 8;
            cpa16((unsigned)__cvta_generic_to_shared(&Ah[s][o][seg]),
                  Wp + (size_t)(o0 + o) * CC + k0 + seg);
        }
        #pragma unroll
        for (int i = 0; i < 2; i++) {
            int c = tid + i * 256;
            int l = c >> 2, seg = (c & 3) * 8;
            cpa16((unsigned)__cvta_generic_to_shared(&Bh[s][l][seg]),
                  Xp + (size_t)(l0 + l) * CC + k0 + seg);
        }
        cpcommit();
    };

    float acc[2][4][4];
    #pragma unroll
    for (int i = 0; i < 2; i++)
        #pragma unroll
        for (int j = 0; j < 4; j++)
            #pragma unroll
            for (int r = 0; r < 4; r++) acc[i][j][r] = 0.f;

    load_stage(0, 0);

    #pragma unroll
    for (int ks = 0; ks < 8; ks++) {
        const int s = ks & 1;
        cpwait<0>();
        __syncthreads();
        if (ks < 7) load_stage(s ^ 1, (ks + 1) * 32);

        #pragma unroll
        for (int kk = 0; kk < 2; kk++) {
            unsigned am[2][4];
            #pragma unroll
            for (int mt = 0; mt < 2; mt++) {
                int ro = om + mt * 16 + g;
                am[mt][0] = *(unsigned*)&Ah[s][ro][kk * 16 + 2 * t];
                am[mt][1] = *(unsigned*)&Ah[s][ro + 8][kk * 16 + 2 * t];
                am[mt][2] = *(unsigned*)&Ah[s][ro][kk * 16 + 2 * t + 8];
                am[mt][3] = *(unsigned*)&Ah[s][ro + 8][kk * 16 + 2 * t + 8];
            }
            #pragma unroll
            for (int nt = 0; nt < 4; nt++) {
                int rl = on + nt * 8 + g;
                unsigned b0 = *(unsigned*)&Bh[s][rl][kk * 16 + 2 * t];
                unsigned b1 = *(unsigned*)&Bh[s][rl][kk * 16 + 2 * t + 8];
                mma_f16(acc[0][nt], am[0], b0, b1);
                mma_f16(acc[1][nt], am[1], b0, b1);
            }
        }
    }

    #pragma unroll
    for (int mt = 0; mt < 2; mt++) {
        int oA = o0 + om + mt * 16 + g;
        int oB = oA + 8;
        float scA = gg[oA] * rsqrtf(var[oA] + EPSV);
        float shA = ((bias[oA] - mean[oA]) * scA + beta[oA]) * outscale;
        scA *= outscale;
        float scB = gg[oB] * rsqrtf(var[oB] + EPSV);
        float shB = ((bias[oB] - mean[oB]) * scB + beta[oB]) * outscale;
        scB *= outscale;
        if (pid == 1) {
            size_t baseA = ((size_t)b * NH + (oA >> 5)) * LSEQ;
            size_t baseB = ((size_t)b * NH + (oB >> 5)) * LSEQ;
            int dA = oA & 31, dB = oB & 31;
            #pragma unroll
            for (int nt = 0; nt < 4; nt++) {
                int col = l0 + on + nt * 8 + 2 * t;
                OUT[(baseA + col) * DH + dA]     = __float2half_rn(acc[mt][nt][0] * scA + shA);
                OUT[(baseA + col + 1) * DH + dA] = __float2half_rn(acc[mt][nt][1] * scA + shA);
                OUT[(baseB + col) * DH + dB]     = __float2half_rn(acc[mt][nt][2] * scB + shB);
                OUT[(baseB + col + 1) * DH + dB] = __float2half_rn(acc[mt][nt][3] * scB + shB);
            }
        } else {
            #pragma unroll
            for (int nt = 0; nt < 4; nt++) {
                int col = l0 + on + nt * 8 + 2 * t;
                unsigned hA = packh2(acc[mt][nt][0] * scA + shA,
                                     acc[mt][nt][1] * scA + shA);
                unsigned hB = packh2(acc[mt][nt][2] * scB + shB,
                                     acc[mt][nt][3] * scB + shB);
                *(unsigned*)&OUT[((size_t)b * CC + oA) * LSEQ + col] = hA;
                *(unsigned*)&OUT[((size_t)b * CC + oB) * LSEQ + col] = hB;
            }
        }
    }
}

// ---------------------------------------------------------------------------
// fp16 flash attention, 128-key chunks (one cpwait+sync per 128 keys),
// processed as four 32-key halves reusing register tiles.
// P in registers; exp f16x2; lsum via ones-MMA. Writes att TRANSPOSED [l][c].
// ---------------------------------------------------------------------------
__global__ __launch_bounds__(128, 4) void attn_f16(
    const __half* __restrict__ qh,
    const __half* __restrict__ kh,
    const __half* __restrict__ vh,
    __half* __restrict__ aht)
{
    __shared__ __align__(16) __half Ks[2][128][40];   // [m][d], 128 keys
    __shared__ __align__(16) __half Vs[2][32][136];   // [d][m], 128 keys

    const int b = blockIdx.z;
    const int h = blockIdx.y;
    const int tid = threadIdx.x, w = tid >> 5, lane = tid & 31;
    const int g = lane >> 2, t = lane & 3;
    const int l0 = blockIdx.x * 128;
    const int qrow = l0 + w * 32 + g;
    const size_t qrowbase = (size_t)b * CC + h * DH;
    const size_t khead = ((size_t)b * NH + h) * LSEQ;
    const __half* Vrow = vh + qrowbase * LSEQ;
    const unsigned ONES2 = 0x3C003C00u;

    unsigned qa[2][2][4];
    #pragma unroll
    for (int mt = 0; mt < 2; mt++) {
        int qr = qrow + mt * 16;
        #pragma unroll
        for (int kk = 0; kk < 2; kk++) {
            int d0 = kk * 16 + 2 * t;
            qa[mt][kk][0] = packh2(__half2float(qh[(qrowbase + d0) * LSEQ + qr]),
                                   __half2float(qh[(qrowbase + d0 + 1) * LSEQ + qr]));
            qa[mt][kk][1] = packh2(__half2float(qh[(qrowbase + d0) * LSEQ + qr + 8]),
                                   __half2float(qh[(qrowbase + d0 + 1) * LSEQ + qr + 8]));
            qa[mt][kk][2] = packh2(__half2float(qh[(qrowbase + d0 + 8) * LSEQ + qr]),
                                   __half2float(qh[(qrowbase + d0 + 9) * LSEQ + qr]));
            qa[mt][kk][3] = packh2(__half2float(qh[(qrowbase + d0 + 8) * LSEQ + qr + 8]),
                                   __half2float(qh[(qrowbase + d0 + 9) * LSEQ + qr + 8]));
        }
    }

    float oc[2][4][4];
    float lsacc[2][4];
    #pragma unroll
    for (int mt = 0; mt < 2; mt++) {
        #pragma unroll
        for (int nt = 0; nt < 4; nt++)
            #pragma unroll
            for (int r = 0; r < 4; r++) oc[mt][nt][r] = 0.f;
        #pragma unroll
        for (int r = 0; r < 4; r++) lsacc[mt][r] = 0.f;
    }

    // prefetch: K 128 rows x 64B (512 x 16B), V 32 rows x 256B (512 x 16B)
    auto prefetch = [&](int s, int mo) {
        #pragma unroll
        for (int i = 0; i < 4; i++) {
            int idx = tid + i * 128;
            int krow = idx >> 2, kseg = idx & 3;
            cpa16((unsigned)__cvta_generic_to_shared(&Ks[s][krow][kseg * 8]),
                  kh + (khead + mo + krow) * DH + kseg * 8);
            int vrow = idx >> 4, vseg = idx & 15;
            cpa16((unsigned)__cvta_generic_to_shared(&Vs[s][vrow][vseg * 8]),
                  Vrow + (size_t)vrow * LSEQ + mo + vseg * 8);
        }
        cpcommit();
    };

    prefetch(0, 0);

    for (int c = 0; c < CHUNKS; c++) {
        const int st = c & 1;
        cpwait<0>();
        __syncthreads();
        if (c < CHUNKS - 1) prefetch(st ^ 1, (c + 1) * 128);

        #pragma unroll
        for (int half = 0; half < 4; half++) {
            const int mbase = half * 32;

            // ---- S = Q*K ----
            float sc[2][4][4];
            #pragma unroll
            for (int mt = 0; mt < 2; mt++)
                #pragma unroll
                for (int nt = 0; nt < 4; nt++)
                    #pragma unroll
                    for (int r = 0; r < 4; r++) sc[mt][nt][r] = 0.f;
            #pragma unroll
            for (int kk = 0; kk < 2; kk++) {
                #pragma unroll
                for (int nt = 0; nt < 4; nt++) {
                    unsigned b0 = *(unsigned*)&Ks[st][mbase + nt * 8 + g][kk * 16 + 2 * t];
                    unsigned b1 = *(unsigned*)&Ks[st][mbase + nt * 8 + g][kk * 16 + 2 * t + 8];
                    mma_f16(sc[0][nt], qa[0][kk], b0, b1);
                    mma_f16(sc[1][nt], qa[1][kk], b0, b1);
                }
            }

            // ---- exp via f16x2 MUFU ----
            unsigned pe2[2][4][2];
            #pragma unroll
            for (int mt = 0; mt < 2; mt++) {
                #pragma unroll
                for (int nt = 0; nt < 4; nt++) {
                    pe2[mt][nt][0] = ex2h2(packh2(sc[mt][nt][0], sc[mt][nt][1]));
                    pe2[mt][nt][1] = ex2h2(packh2(sc[mt][nt][2], sc[mt][nt][3]));
                }
            }

            // ---- O += P*V ; lsum ones-MMA ----
            #pragma unroll
            for (int kk = 0; kk < 2; kk++) {
                unsigned pa[2][4];
                #pragma unroll
                for (int mt = 0; mt < 2; mt++) {
                    pa[mt][0] = pe2[mt][2 * kk][0];
                    pa[mt][1] = pe2[mt][2 * kk][1];
                    pa[mt][2] = pe2[mt][2 * kk + 1][0];
                    pa[mt][3] = pe2[mt][2 * kk + 1][1];
                }
                #pragma unroll
                for (int nt = 0; nt < 4; nt++) {
                    unsigned b0 = *(unsigned*)&Vs[st][nt * 8 + g][mbase + kk * 16 + 2 * t];
                    unsigned b1 = *(unsigned*)&Vs[st][nt * 8 + g][mbase + kk * 16 + 2 * t + 8];
                    mma_f16(oc[0][nt], pa[0], b0, b1);
                    mma_f16(oc[1][nt], pa[1], b0, b1);
                }
                mma_f16(lsacc[0], pa[0], ONES2, ONES2);
                mma_f16(lsacc[1], pa[1], ONES2, ONES2);
            }
        }
    }

    // writeback att TRANSPOSED: aht[b][l][c], c = h*32+d
    __half* ab = aht + ((size_t)b * LSEQ) * CC + h * DH;
    #pragma unroll
    for (int mt = 0; mt < 2; mt++) {
        int qr = qrow + mt * 16;
        float inv0 = 1.f / lsacc[mt][0];
        float inv1 = 1.f / lsacc[mt][2];
        #pragma unroll
        for (int nt = 0; nt < 4; nt++) {
            int d0 = nt * 8 + 2 * t;
            *(unsigned*)&ab[(size_t)qr * CC + d0] =
                packh2(oc[mt][nt][0] * inv0, oc[mt][nt][1] * inv0);
            *(unsigned*)&ab[(size_t)(qr + 8) * CC + d0] =
                packh2(oc[mt][nt][2] * inv1, oc[mt][nt][3] * inv1);
        }
    }
}

// ---------------------------------------------------------------------------
// Output projection: all-f16 MMA (wo half, att^T half) + bias + residual.
// ---------------------------------------------------------------------------
__global__ __launch_bounds__(256, 2) void outproj_f16(
    const __half* __restrict__ wh,     // wo at pid 3
    const __half* __restrict__ aht,    // [b][l][c]
    const float* __restrict__ bias,
    const float* __restrict__ Qres,
    float* __restrict__ OUT)
{
    __shared__ __align__(16) __half Ah[2][64][40];
    __shared__ __align__(16) __half Bh[2][128][40];

    const int b  = blockIdx.z;
    const int o0 = blockIdx.y * 64;
    const int l0 = blockIdx.x * 128;
    const int tid = threadIdx.x;
    const int w = tid >> 5, lane = tid & 31;
    const int g = lane >> 2, t = lane & 3;
    const int om = (w >> 2) * 32;
    const int on = (w & 3) * 32;

    const __half* Wp = wh + 3 * CC * CC;
    const __half* Ap = aht + (size_t)b * LSEQ * CC;

    auto load_stage = [&](int s, int k0) {
        {
            int o = tid >> 2, seg = (tid & 3) * 8;
            cpa16((unsigned)__cvta_generic_to_shared(&Ah[s][o][seg]),
                  Wp + (size_t)(o0 + o) * CC + k0 + seg);
        }
        #pragma unroll
        for (int i = 0; i < 2; i++) {
            int c = tid + i * 256;
            int l = c >> 2, seg = (c & 3) * 8;
            cpa16((unsigned)__cvta_generic_to_shared(&Bh[s][l][seg]),
                  Ap + (size_t)(l0 + l) * CC + k0 + seg);
        }
        cpcommit();
    };

    float acc[2][4][4];
    #pragma unroll
    for (int i = 0; i < 2; i++)
        #pragma unroll
        for (int j = 0; j < 4; j++)
            #pragma unroll
            for (int r = 0; r < 4; r++) acc[i][j][r] = 0.f;

    load_stage(0, 0);

    #pragma unroll
    for (int ks = 0; ks < 8; ks++) {
        const int s = ks & 1;
        cpwait<0>();
        __syncthreads();
        if (ks < 7) load_stage(s ^ 1, (ks + 1) * 32);

        #pragma unroll
        for (int kk = 0; kk < 2; kk++) {
            unsigned am[2][4];
            #pragma unroll
            for (int mt = 0; mt < 2; mt++) {
                int ro = om + mt * 16 + g;
                am[mt][0] = *(unsigned*)&Ah[s][ro][kk * 16 + 2 * t];
                am[mt][1] = *(unsigned*)&Ah[s][ro + 8][kk * 16 + 2 * t];
                am[mt][2] = *(unsigned*)&Ah[s][ro][kk * 16 + 2 * t + 8];
                am[mt][3] = *(unsigned*)&Ah[s][ro + 8][kk * 16 + 2 * t + 8];
            }
            #pragma unroll
            for (int nt = 0; nt < 4; nt++) {
                int rl = on + nt * 8 + g;
                unsigned b0 = *(unsigned*)&Bh[s][rl][kk * 16 + 2 * t];
                unsigned b1 = *(unsigned*)&Bh[s][rl][kk * 16 + 2 * t + 8];
                mma_f16(acc[0][nt], am[0], b0, b1);
                mma_f16(acc[1][nt], am[1], b0, b1);
            }
        }
    }

    #pragma unroll
    for (int mt = 0; mt < 2; mt++) {
        int oA = o0 + om + mt * 16 + g;
        int oB = oA + 8;
        float bA = bias[oA], bBv = bias[oB];
        #pragma unroll
        for (int nt = 0; nt < 4; nt++) {
            int col = l0 + on + nt * 8 + 2 * t;
            size_t iA = ((size_t)b * CC + oA) * LSEQ + col;
            size_t iB = ((size_t)b * CC + oB) * LSEQ + col;
            float2 qA = *(const float2*)&Qres[iA];
            float2 qB = *(const float2*)&Qres[iB];
            float2 rA = {acc[mt][nt][0] + bA + qA.x, acc[mt][nt][1] + bA + qA.y};
            float2 rB = {acc[mt][nt][2] + bBv + qB.x, acc[mt][nt][3] + bBv + qB.y};
            *(float2*)&OUT[iA] = rA;
            *(float2*)&OUT[iB] = rB;
        }
    }
}

// ---------------------------------------------------------------------------
extern "C" void kernel_launch(void* const* d_in, const int* in_sizes, int n_in,
                              void* d_out, int out_size)
{
    const float* v     = (const float*)d_in[0];
    const float* k     = (const float*)d_in[1];
    const float* q     = (const float*)d_in[2];
    const float* pe_q  = (const float*)d_in[3];
    const float* pe_vk = (const float*)d_in[4];
    const float* wq = (const float*)d_in[5];
    const float* bq = (const float*)d_in[6];
    const float* gq = (const float*)d_in[7];
    const float* betaq = (const float*)d_in[8];
    const float* mq = (const float*)d_in[9];
    const float* varq = (const float*)d_in[10];
    const float* wk = (const float*)d_in[11];
    const float* bk = (const float*)d_in[12];
    const float* gk = (const float*)d_in[13];
    const float* betak = (const float*)d_in[14];
    const float* mk = (const float*)d_in[15];
    const float* vark = (const float*)d_in[16];
    const float* wv = (const float*)d_in[17];
    const float* bv = (const float*)d_in[18];
    const float* gv = (const float*)d_in[19];
    const float* betav = (const float*)d_in[20];
    const float* mv = (const float*)d_in[21];
    const float* varv = (const float*)d_in[22];
    const float* wo = (const float*)d_in[23];
    const float* bo = (const float*)d_in[24];
    float* out = (float*)d_out;

    __half *wh, *xpet, *qh, *kh, *vh, *aht;
    cudaGetSymbolAddress((void**)&wh,   g_wh);
    cudaGetSymbolAddress((void**)&xpet, g_xpet);
    cudaGetSymbolAddress((void**)&qh,   g_qh);
    cudaGetSymbolAddress((void**)&kh,   g_kh);
    cudaGetSymbolAddress((void**)&vh,   g_vh);
    cudaGetSymbolAddress((void**)&aht,  g_aht);

    // 1/sqrt(32) * log2(e) -> softmax via bare ex2
    const float qsc = 0.17677669529663687f * 1.4426950408889634f;

    dim3 cw_grid(CC * CC / (256 * 4), 4);          // 64 x 4
    conv_w<<<cw_grid, 256>>>(wq, wk, wv, wo, wh);

    dim3 px_grid(LSEQ / 32, CC / 32, 3 * BB);      // 64 x 8 x 12
    prep_xpe<<<px_grid, 256>>>(q, k, v, pe_q, pe_vk, xpet);

    dim3 proj_grid(LSEQ / 128, CC / 64, 3 * BB);   // 16 x 4 x 12
    proj_all<<<proj_grid, 256>>>(wh, xpet,
                                 bq, gq, betaq, mq, varq,
                                 bk, gk, betak, mk, vark,
                                 bv, gv, betav, mv, varv,
                                 qsc, qh, kh, vh);

    dim3 attn_grid(LSEQ / 128, NH, BB);            // 16 x 8 x 4
    attn_f16<<<attn_grid, 128>>>(qh, kh, vh, aht);

    dim3 out_grid(LSEQ / 128, CC / 64, BB);        // 16 x 4 x 4
    outproj_f16<<<out_grid, 256>>>(wh, aht, bo, q, out);
}

// round 17
// speedup vs baseline: 1.0003x; 1.0003x over previous
#include <cuda_runtime.h>
#include <cuda_fp16.h>
#include <cstddef>

#define BB 4
#define CC 256
#define LSEQ 2048
#define NH 8
#define DH 32
#define EPSV 1e-5f
#define CHUNKS (LSEQ / 64)               // 32 chunks of 64 keys

// ---- helpers --------------------------------------------------------------
// m16n8k16 f16 MMA, fp32 accum
__device__ __forceinline__ void mma_f16(float* d, const unsigned* a,
                                        unsigned b0, unsigned b1) {
    asm("mma.sync.aligned.m16n8k16.row.col.f32.f16.f16.f32 "
        "{%0,%1,%2,%3},{%4,%5,%6,%7},{%8,%9},{%0,%1,%2,%3};"
        : "+f"(d[0]), "+f"(d[1]), "+f"(d[2]), "+f"(d[3])
        : "r"(a[0]), "r"(a[1]), "r"(a[2]), "r"(a[3]), "r"(b0), "r"(b1));
}
__device__ __forceinline__ unsigned packh2(float a, float b) {
    __half2 h = __floats2half2_rn(a, b);
    return *(unsigned*)&h;
}
__device__ __forceinline__ unsigned ex2h2(unsigned x) {
    unsigned y;
    asm("ex2.approx.f16x2 %0,%1;" : "=r"(y) : "r"(x));
    return y;
}
__device__ __forceinline__ void cpa16(unsigned dst, const void* src) {
    asm volatile("cp.async.cg.shared.global [%0], [%1], 16;" :: "r"(dst), "l"(src));
}
__device__ __forceinline__ void cpcommit() {
    asm volatile("cp.async.commit_group;");
}
template <int N>
__device__ __forceinline__ void cpwait() {
    asm volatile("cp.async.wait_group %0;" :: "n"(N));
}

// Scratch
__device__ __half g_wh[4 * CC * CC];              // wq,wk,wv,wo in half [o][k]
__device__ __half g_xpet[3 * BB * LSEQ * CC];     // (X+PE)^T half [pid][b][l][c]
__device__ __half g_qh[BB * CC * LSEQ];           // [b][h*32+d][l]
__device__ __half g_kh[BB * NH * LSEQ * DH];      // [b][h][m][d]
__device__ __half g_vh[BB * CC * LSEQ];           // [b][h*32+d][m]
__device__ __half g_aht[BB * LSEQ * CC];          // att TRANSPOSED [b][l][c]

// ---------------------------------------------------------------------------
// Prepass 1: convert wq/wk/wv/wo to half.
// ---------------------------------------------------------------------------
__global__ __launch_bounds__(256) void conv_w(
    const float* __restrict__ wq, const float* __restrict__ wk,
    const float* __restrict__ wv, const float* __restrict__ wo,
    __half* __restrict__ wh)
{
    const int pid = blockIdx.y;
    const float* W = pid == 0 ? wq : (pid == 1 ? wk : (pid == 2 ? wv : wo));
    int i = (blockIdx.x * 256 + threadIdx.x) * 4;
    float4 f = *(const float4*)&W[i];
    __half2 h0 = __floats2half2_rn(f.x, f.y);
    __half2 h1 = __floats2half2_rn(f.z, f.w);
    __half2* dst = (__half2*)&wh[pid * CC * CC + i];
    dst[0] = h0;
    dst[1] = h1;
}

// ---------------------------------------------------------------------------
// Prepass 2: XPE^T[pid][b][l][c] = half(X[b][c][l] + PE[c][l]).  32x32 tiles.
// ---------------------------------------------------------------------------
__global__ __launch_bounds__(256) void prep_xpe(
    const float* __restrict__ qx, const float* __restrict__ kx,
    const float* __restrict__ vx,
    const float* __restrict__ pe_q, const float* __restrict__ pe_vk,
    __half* __restrict__ xpet)
{
    __shared__ float T[32][33];
    const int pid = blockIdx.z / BB;
    const int b   = blockIdx.z % BB;
    const int c0 = blockIdx.y * 32, l0 = blockIdx.x * 32;
    const int tid = threadIdx.x;
    const float* X  = pid == 0 ? qx : (pid == 1 ? kx : vx);
    const float* PE = pid == 0 ? pe_q : pe_vk;

    #pragma unroll
    for (int i = tid; i < 1024; i += 256) {
        int c = i >> 5, l = i & 31;
        size_t off = (size_t)(c0 + c) * LSEQ + l0 + l;
        T[c][l] = X[(size_t)b * CC * LSEQ + off] + PE[off];
    }
    __syncthreads();
    #pragma unroll
    for (int i = tid; i < 1024; i += 256) {
        int l = i >> 5, c = i & 31;
        xpet[((size_t)(pid * BB + b) * LSEQ + l0 + l) * CC + c0 + c] =
            __float2half_rn(T[c][l]);
    }
}

// ---------------------------------------------------------------------------
// Fused Q/K/V projection: all-f16 MMA, cp.async double-buffered.
// ---------------------------------------------------------------------------
__global__ __launch_bounds__(256, 2) void proj_all(
    const __half* __restrict__ wh, const __half* __restrict__ xpet,
    const float* __restrict__ bq, const float* __restrict__ gq,
    const float* __restrict__ betaq, const float* __restrict__ mq,
    const float* __restrict__ varq,
    const float* __restrict__ bk, const float* __restrict__ gk,
    const float* __restrict__ betak, const float* __restrict__ mk,
    const float* __restrict__ vark,
    const float* __restrict__ bv, const float* __restrict__ gv,
    const float* __restrict__ betav, const float* __restrict__ mv,
    const float* __restrict__ varv,
    float qsc,
    __half* __restrict__ qh, __half* __restrict__ kh, __half* __restrict__ vh)
{
    __shared__ __align__(16) __half Ah[2][64][40];    // [o][kk]
    __shared__ __align__(16) __half Bh[2][128][40];   // [l][kk]

    const int pid = blockIdx.z / BB;
    const int b   = blockIdx.z % BB;
    const int o0 = blockIdx.y * 64;
    const int l0 = blockIdx.x * 128;
    const int tid = threadIdx.x;
    const int w = tid >> 5, lane = tid & 31;
    const int g = lane >> 2, t = lane & 3;
    const int om = (w >> 2) * 32;
    const int on = (w & 3) * 32;

    const float *bias, *gg, *beta, *mean, *var;
    __half* OUT;
    float outscale;
    if (pid == 0) {
        bias = bq; gg = gq; beta = betaq; mean = mq; var = varq;
        outscale = qsc; OUT = qh;
    } else if (pid == 1) {
        bias = bk; gg = gk; beta = betak; mean = mk; var = vark;
        outscale = 1.f; OUT = kh;
    } else {
        bias = bv; gg = gv; beta = betav; mean = mv; var = varv;
        outscale = 1.f; OUT = vh;
    }
    const __half* Wp = wh + pid * CC * CC;
    const __half* Xp = xpet + (size_t)(pid * BB + b) * LSEQ * CC;

    auto load_stage = [&](int s, int k0) {
        {
            int o = tid >> 2, seg = (tid & 3) * 8;
            cpa16((unsigned)__cvta_generic_to_shared(&Ah[s][o][seg]),
                  Wp + (size_t)(o0 + o) * CC + k0 + seg);
        }
        #pragma unroll
        for (int i = 0; i < 2; i++) {
            int c = tid + i * 256;
            int l = c >> 2, seg = (c & 3) * 8;
            cpa16((unsigned)__cvta_generic_to_shared(&Bh[s][l][seg]),
                  Xp + (size_t)(l0 + l) * CC + k0 + seg);
        }
        cpcommit();
    };

    float acc[2][4][4];
    #pragma unroll
    for (int i = 0; i < 2; i++)
        #pragma unroll
        for (int j = 0; j < 4; j++)
            #pragma unroll
            for (int r = 0; r < 4; r++) acc[i][j][r] = 0.f;

    load_stage(0, 0);

    #pragma unroll
    for (int ks = 0; ks < 8; ks++) {
        const int s = ks & 1;
        cpwait<0>();
        __syncthreads();
        if (ks < 7) load_stage(s ^ 1, (ks + 1) * 32);

        #pragma unroll
        for (int kk = 0; kk < 2; kk++) {
            unsigned am[2][4];
            #pragma unroll
            for (int mt = 0; mt < 2; mt++) {
                int ro = om + mt * 16 + g;
                am[mt][0] = *(unsigned*)&Ah[s][ro][kk * 16 + 2 * t];
                am[mt][1] = *(unsigned*)&Ah[s][ro + 8][kk * 16 + 2 * t];
                am[mt][2] = *(unsigned*)&Ah[s][ro][kk * 16 + 2 * t + 8];
                am[mt][3] = *(unsigned*)&Ah[s][ro + 8][kk * 16 + 2 * t + 8];
            }
            #pragma unroll
            for (int nt = 0; nt < 4; nt++) {
                int rl = on + nt * 8 + g;
                unsigned b0 = *(unsigned*)&Bh[s][rl][kk * 16 + 2 * t];
                unsigned b1 = *(unsigned*)&Bh[s][rl][kk * 16 + 2 * t + 8];
                mma_f16(acc[0][nt], am[0], b0, b1);
                mma_f16(acc[1][nt], am[1], b0, b1);
            }
        }
    }

    #pragma unroll
    for (int mt = 0; mt < 2; mt++) {
        int oA = o0 + om + mt * 16 + g;
        int oB = oA + 8;
        float scA = gg[oA] * rsqrtf(var[oA] + EPSV);
        float shA = ((bias[oA] - mean[oA]) * scA + beta[oA]) * outscale;
        scA *= outscale;
        float scB = gg[oB] * rsqrtf(var[oB] + EPSV);
        float shB = ((bias[oB] - mean[oB]) * scB + beta[oB]) * outscale;
        scB *= outscale;
        if (pid == 1) {
            size_t baseA = ((size_t)b * NH + (oA >> 5)) * LSEQ;
            size_t baseB = ((size_t)b * NH + (oB >> 5)) * LSEQ;
            int dA = oA & 31, dB = oB & 31;
            #pragma unroll
            for (int nt = 0; nt < 4; nt++) {
                int col = l0 + on + nt * 8 + 2 * t;
                OUT[(baseA + col) * DH + dA]     = __float2half_rn(acc[mt][nt][0] * scA + shA);
                OUT[(baseA + col + 1) * DH + dA] = __float2half_rn(acc[mt][nt][1] * scA + shA);
                OUT[(baseB + col) * DH + dB]     = __float2half_rn(acc[mt][nt][2] * scB + shB);
                OUT[(baseB + col + 1) * DH + dB] = __float2half_rn(acc[mt][nt][3] * scB + shB);
            }
        } else {
            #pragma unroll
            for (int nt = 0; nt < 4; nt++) {
                int col = l0 + on + nt * 8 + 2 * t;
                unsigned hA = packh2(acc[mt][nt][0] * scA + shA,
                                     acc[mt][nt][1] * scA + shA);
                unsigned hB = packh2(acc[mt][nt][2] * scB + shB,
                                     acc[mt][nt][3] * scB + shB);
                *(unsigned*)&OUT[((size_t)b * CC + oA) * LSEQ + col] = hA;
                *(unsigned*)&OUT[((size_t)b * CC + oB) * LSEQ + col] = hB;
            }
        }
    }
}

// ---------------------------------------------------------------------------
// fp16 flash attention, 16 queries/warp, 64-query blocks (grid 1024),
// 6 CTAs/SM for latency hiding. 64-key chunks, two 32-key halves each.
// P in registers; exp f16x2; lsum via ones-MMA. Writes att TRANSPOSED [l][c].
// ---------------------------------------------------------------------------
__global__ __launch_bounds__(128, 6) void attn_f16(
    const __half* __restrict__ qh,
    const __half* __restrict__ kh,
    const __half* __restrict__ vh,
    __half* __restrict__ aht)
{
    __shared__ __align__(16) __half Ks[2][64][40];   // [m][d], 64 keys
    __shared__ __align__(16) __half Vs[2][32][72];   // [d][m], 64 keys

    const int b = blockIdx.z;
    const int h = blockIdx.y;
    const int tid = threadIdx.x, w = tid >> 5, lane = tid & 31;
    const int g = lane >> 2, t = lane & 3;
    const int l0 = blockIdx.x * 64;
    const int qrow = l0 + w * 16 + g;
    const size_t qrowbase = (size_t)b * CC + h * DH;
    const size_t khead = ((size_t)b * NH + h) * LSEQ;
    const __half* Vrow = vh + qrowbase * LSEQ;
    const unsigned ONES2 = 0x3C003C00u;

    // Q A-frags: one 16-row M-tile per warp
    unsigned qa[2][4];
    #pragma unroll
    for (int kk = 0; kk < 2; kk++) {
        int d0 = kk * 16 + 2 * t;
        qa[kk][0] = packh2(__half2float(qh[(qrowbase + d0) * LSEQ + qrow]),
                           __half2float(qh[(qrowbase + d0 + 1) * LSEQ + qrow]));
        qa[kk][1] = packh2(__half2float(qh[(qrowbase + d0) * LSEQ + qrow + 8]),
                           __half2float(qh[(qrowbase + d0 + 1) * LSEQ + qrow + 8]));
        qa[kk][2] = packh2(__half2float(qh[(qrowbase + d0 + 8) * LSEQ + qrow]),
                           __half2float(qh[(qrowbase + d0 + 9) * LSEQ + qrow]));
        qa[kk][3] = packh2(__half2float(qh[(qrowbase + d0 + 8) * LSEQ + qrow + 8]),
                           __half2float(qh[(qrowbase + d0 + 9) * LSEQ + qrow + 8]));
    }

    float oc[4][4];
    float lsacc[4];
    #pragma unroll
    for (int nt = 0; nt < 4; nt++)
        #pragma unroll
        for (int r = 0; r < 4; r++) oc[nt][r] = 0.f;
    #pragma unroll
    for (int r = 0; r < 4; r++) lsacc[r] = 0.f;

    // prefetch: K 64 rows x 64B (256 x 16B), V 32 rows x 128B (256 x 16B)
    auto prefetch = [&](int s, int mo) {
        #pragma unroll
        for (int i = 0; i < 2; i++) {
            int idx = tid + i * 128;
            int krow = idx >> 2, kseg = idx & 3;
            cpa16((unsigned)__cvta_generic_to_shared(&Ks[s][krow][kseg * 8]),
                  kh + (khead + mo + krow) * DH + kseg * 8);
            int vrow = idx >> 3, vseg = idx & 7;
            cpa16((unsigned)__cvta_generic_to_shared(&Vs[s][vrow][vseg * 8]),
                  Vrow + (size_t)vrow * LSEQ + mo + vseg * 8);
        }
        cpcommit();
    };

    prefetch(0, 0);

    for (int c = 0; c < CHUNKS; c++) {
        const int st = c & 1;
        cpwait<0>();
        __syncthreads();
        if (c < CHUNKS - 1) prefetch(st ^ 1, (c + 1) * 64);

        #pragma unroll
        for (int half = 0; half < 2; half++) {
            const int mbase = half * 32;

            // ---- S = Q*K ----
            float sc[4][4];
            #pragma unroll
            for (int nt = 0; nt < 4; nt++)
                #pragma unroll
                for (int r = 0; r < 4; r++) sc[nt][r] = 0.f;
            #pragma unroll
            for (int kk = 0; kk < 2; kk++) {
                #pragma unroll
                for (int nt = 0; nt < 4; nt++) {
                    unsigned b0 = *(unsigned*)&Ks[st][mbase + nt * 8 + g][kk * 16 + 2 * t];
                    unsigned b1 = *(unsigned*)&Ks[st][mbase + nt * 8 + g][kk * 16 + 2 * t + 8];
                    mma_f16(sc[nt], qa[kk], b0, b1);
                }
            }

            // ---- exp via f16x2 MUFU ----
            unsigned pe2[4][2];
            #pragma unroll
            for (int nt = 0; nt < 4; nt++) {
                pe2[nt][0] = ex2h2(packh2(sc[nt][0], sc[nt][1]));
                pe2[nt][1] = ex2h2(packh2(sc[nt][2], sc[nt][3]));
            }

            // ---- O += P*V ; lsum ones-MMA ----
            #pragma unroll
            for (int kk = 0; kk < 2; kk++) {
                unsigned pa[4] = {pe2[2 * kk][0], pe2[2 * kk][1],
                                  pe2[2 * kk + 1][0], pe2[2 * kk + 1][1]};
                #pragma unroll
                for (int nt = 0; nt < 4; nt++) {
                    unsigned b0 = *(unsigned*)&Vs[st][nt * 8 + g][mbase + kk * 16 + 2 * t];
                    unsigned b1 = *(unsigned*)&Vs[st][nt * 8 + g][mbase + kk * 16 + 2 * t + 8];
                    mma_f16(oc[nt], pa, b0, b1);
                }
                mma_f16(lsacc, pa, ONES2, ONES2);
            }
        }
    }

    // writeback att TRANSPOSED: aht[b][l][c], c = h*32+d
    __half* ab = aht + ((size_t)b * LSEQ) * CC + h * DH;
    {
        float inv0 = 1.f / lsacc[0];
        float inv1 = 1.f / lsacc[2];
        #pragma unroll
        for (int nt = 0; nt < 4; nt++) {
            int d0 = nt * 8 + 2 * t;
            *(unsigned*)&ab[(size_t)qrow * CC + d0] =
                packh2(oc[nt][0] * inv0, oc[nt][1] * inv0);
            *(unsigned*)&ab[(size_t)(qrow + 8) * CC + d0] =
                packh2(oc[nt][2] * inv1, oc[nt][3] * inv1);
        }
    }
}

// ---------------------------------------------------------------------------
// Output projection: all-f16 MMA (wo half, att^T half) + bias + residual.
// ---------------------------------------------------------------------------
__global__ __launch_bounds__(256, 2) void outproj_f16(
    const __half* __restrict__ wh,     // wo at pid 3
    const __half* __restrict__ aht,    // [b][l][c]
    const float* __restrict__ bias,
    const float* __restrict__ Qres,
    float* __restrict__ OUT)
{
    __shared__ __align__(16) __half Ah[2][64][40];
    __shared__ __align__(16) __half Bh[2][128][40];

    const int b  = blockIdx.z;
    const int o0 = blockIdx.y * 64;
    const int l0 = blockIdx.x * 128;
    const int tid = threadIdx.x;
    const int w = tid >> 5, lane = tid & 31;
    const int g = lane >> 2, t = lane & 3;
    const int om = (w >> 2) * 32;
    const int on = (w & 3) * 32;

    const __half* Wp = wh + 3 * CC * CC;
    const __half* Ap = aht + (size_t)b * LSEQ * CC;

    auto load_stage = [&](int s, int k0) {
        {
            int o = tid >> 2, seg = (tid & 3) * 8;
            cpa16((unsigned)__cvta_generic_to_shared(&Ah[s][o][seg]),
                  Wp + (size_t)(o0 + o) * CC + k0 + seg);
        }
        #pragma unroll
        for (int i = 0; i < 2; i++) {
            int c = tid + i * 256;
            int l = c >> 2, seg = (c & 3) * 8;
            cpa16((unsigned)__cvta_generic_to_shared(&Bh[s][l][seg]),
                  Ap + (size_t)(l0 + l) * CC + k0 + seg);
        }
        cpcommit();
    };

    float acc[2][4][4];
    #pragma unroll
    for (int i = 0; i < 2; i++)
        #pragma unroll
        for (int j = 0; j < 4; j++)
            #pragma unroll
            for (int r = 0; r < 4; r++) acc[i][j][r] = 0.f;

    load_stage(0, 0);

    #pragma unroll
    for (int ks = 0; ks < 8; ks++) {
        const int s = ks & 1;
        cpwait<0>();
        __syncthreads();
        if (ks < 7) load_stage(s ^ 1, (ks + 1) * 32);

        #pragma unroll
        for (int kk = 0; kk < 2; kk++) {
            unsigned am[2][4];
            #pragma unroll
            for (int mt = 0; mt < 2; mt++) {
                int ro = om + mt * 16 + g;
                am[mt][0] = *(unsigned*)&Ah[s][ro][kk * 16 + 2 * t];
                am[mt][1] = *(unsigned*)&Ah[s][ro + 8][kk * 16 + 2 * t];
                am[mt][2] = *(unsigned*)&Ah[s][ro][kk * 16 + 2 * t + 8];
                am[mt][3] = *(unsigned*)&Ah[s][ro + 8][kk * 16 + 2 * t + 8];
            }
            #pragma unroll
            for (int nt = 0; nt < 4; nt++) {
                int rl = on + nt * 8 + g;
                unsigned b0 = *(unsigned*)&Bh[s][rl][kk * 16 + 2 * t];
                unsigned b1 = *(unsigned*)&Bh[s][rl][kk * 16 + 2 * t + 8];
                mma_f16(acc[0][nt], am[0], b0, b1);
                mma_f16(acc[1][nt], am[1], b0, b1);
            }
        }
    }

    #pragma unroll
    for (int mt = 0; mt < 2; mt++) {
        int oA = o0 + om + mt * 16 + g;
        int oB = oA + 8;
        float bA = bias[oA], bBv = bias[oB];
        #pragma unroll
        for (int nt = 0; nt < 4; nt++) {
            int col = l0 + on + nt * 8 + 2 * t;
            size_t iA = ((size_t)b * CC + oA) * LSEQ + col;
            size_t iB = ((size_t)b * CC + oB) * LSEQ + col;
            float2 qA = *(const float2*)&Qres[iA];
            float2 qB = *(const float2*)&Qres[iB];
            float2 rA = {acc[mt][nt][0] + bA + qA.x, acc[mt][nt][1] + bA + qA.y};
            float2 rB = {acc[mt][nt][2] + bBv + qB.x, acc[mt][nt][3] + bBv + qB.y};
            *(float2*)&OUT[iA] = rA;
            *(float2*)&OUT[iB] = rB;
        }
    }
}

// ---------------------------------------------------------------------------
extern "C" void kernel_launch(void* const* d_in, const int* in_sizes, int n_in,
                              void* d_out, int out_size)
{
    const float* v     = (const float*)d_in[0];
    const float* k     = (const float*)d_in[1];
    const float* q     = (const float*)d_in[2];
    const float* pe_q  = (const float*)d_in[3];
    const float* pe_vk = (const float*)d_in[4];
    const float* wq = (const float*)d_in[5];
    const float* bq = (const float*)d_in[6];
    const float* gq = (const float*)d_in[7];
    const float* betaq = (const float*)d_in[8];
    const float* mq = (const float*)d_in[9];
    const float* varq = (const float*)d_in[10];
    const float* wk = (const float*)d_in[11];
    const float* bk = (const float*)d_in[12];
    const float* gk = (const float*)d_in[13];
    const float* betak = (const float*)d_in[14];
    const float* mk = (const float*)d_in[15];
    const float* vark = (const float*)d_in[16];
    const float* wv = (const float*)d_in[17];
    const float* bv = (const float*)d_in[18];
    const float* gv = (const float*)d_in[19];
    const float* betav = (const float*)d_in[20];
    const float* mv = (const float*)d_in[21];
    const float* varv = (const float*)d_in[22];
    const float* wo = (const float*)d_in[23];
    const float* bo = (const float*)d_in[24];
    float* out = (float*)d_out;

    __half *wh, *xpet, *qh, *kh, *vh, *aht;
    cudaGetSymbolAddress((void**)&wh,   g_wh);
    cudaGetSymbolAddress((void**)&xpet, g_xpet);
    cudaGetSymbolAddress((void**)&qh,   g_qh);
    cudaGetSymbolAddress((void**)&kh,   g_kh);
    cudaGetSymbolAddress((void**)&vh,   g_vh);
    cudaGetSymbolAddress((void**)&aht,  g_aht);

    // 1/sqrt(32) * log2(e) -> softmax via bare ex2
    const float qsc = 0.17677669529663687f * 1.4426950408889634f;

    dim3 cw_grid(CC * CC / (256 * 4), 4);          // 64 x 4
    conv_w<<<cw_grid, 256>>>(wq, wk, wv, wo, wh);

    dim3 px_grid(LSEQ / 32, CC / 32, 3 * BB);      // 64 x 8 x 12
    prep_xpe<<<px_grid, 256>>>(q, k, v, pe_q, pe_vk, xpet);

    dim3 proj_grid(LSEQ / 128, CC / 64, 3 * BB);   // 16 x 4 x 12
    proj_all<<<proj_grid, 256>>>(wh, xpet,
                                 bq, gq, betaq, mq, varq,
                                 bk, gk, betak, mk, vark,
                                 bv, gv, betav, mv, varv,
                                 qsc, qh, kh, vh);

    dim3 attn_grid(LSEQ / 64, NH, BB);             // 32 x 8 x 4 = 1024
    attn_f16<<<attn_grid, 128>>>(qh, kh, vh, aht);

    dim3 out_grid(LSEQ / 128, CC / 64, BB);        // 16 x 4 x 4
    outproj_f16<<<out_grid, 256>>>(wh, aht, bo, q, out);
}